// round 4
// baseline (speedup 1.0000x reference)
#include <cuda_runtime.h>

// Problem constants (fixed by the reference)
#define BDIM  4
#define HDIM  496
#define WDIM  432
#define NPTS  400000
#define CCH   128
#define HWSZ  (HDIM * WDIM)            // 214272
#define GRID_ELEMS (BDIM * HWSZ)       // 857088 (divisible by 4)
#define NTAPS 49                       // 7x7

// Scratch (no allocations allowed anywhere in this file)
__device__ int    g_grid[GRID_ELEMS];  // 3.43 MB, fits L2
__device__ float2 g_cat[NPTS];         // 3.20 MB, fits L2

// ---------------------------------------------------------------------------
// Kernel 0: reset grid to -1 (deterministic; graph-replayed every iteration)
// ---------------------------------------------------------------------------
__global__ void __launch_bounds__(256) fill_grid_kernel() {
    int i = blockIdx.x * blockDim.x + threadIdx.x;
    // GRID_ELEMS/4 = 214272 int4 stores; launched with exactly that many threads
    reinterpret_cast<int4*>(g_grid)[i] = make_int4(-1, -1, -1, -1);
}

// ---------------------------------------------------------------------------
// Kernel 1: per-point (mean, max) over 128 channels + scatter index into grid
// One warp per point. Lane l loads float4 = channels [4l, 4l+3].
// ---------------------------------------------------------------------------
__global__ void __launch_bounds__(256)
reduce_scatter_kernel(const float4* __restrict__ feat4,
                      const int*    __restrict__ idx) {
    int gtid = blockIdx.x * blockDim.x + threadIdx.x;
    int warp = gtid >> 5;
    int lane = threadIdx.x & 31;
    if (warp >= NPTS) return;

    float4 f = feat4[warp * 32 + lane];
    float s = (f.x + f.y) + (f.z + f.w);
    float m = fmaxf(fmaxf(f.x, f.y), fmaxf(f.z, f.w));
#pragma unroll
    for (int o = 16; o > 0; o >>= 1) {
        s += __shfl_xor_sync(0xFFFFFFFFu, s, o);
        m  = fmaxf(m, __shfl_xor_sync(0xFFFFFFFFu, m, o));
    }
    if (lane == 0) {
        g_cat[warp] = make_float2(s * (1.0f / 128.0f), m);
        int b = idx[warp * 3 + 0];
        int y = idx[warp * 3 + 1];
        int x = idx[warp * 3 + 2];
        g_grid[b * HWSZ + y * WDIM + x] = warp;
    }
}

// ---------------------------------------------------------------------------
// Kernel 2: 7x7 gather of neighbor (avg,max), dot with weight, sigmoid, scale.
// One warp per point. Lane l handles taps l and l+32 (if < 49).
// ---------------------------------------------------------------------------
__device__ __forceinline__ float tap_contrib(int t, int y, int x,
                                             const int* __restrict__ gb,
                                             const float* __restrict__ sw) {
    int dy = t / 7 - 3;
    int dx = t % 7 - 3;
    int ny = y + dy;
    int nx = x + dx;
    float r = 0.0f;
    if (ny >= 0 && ny < HDIM && nx >= 0 && nx < WDIM) {
        int nbr = __ldg(gb + ny * WDIM + nx);
        if (nbr >= 0) {
            float2 c = g_cat[nbr];
            r = c.x * sw[2 * t] + c.y * sw[2 * t + 1];
        }
    }
    return r;
}

__global__ void __launch_bounds__(256)
conv_scale_kernel(const float4* __restrict__ feat4,
                  const float*  __restrict__ weight,   // 98 floats, (49,2)
                  const int*    __restrict__ idx,
                  float4*       __restrict__ out4) {
    __shared__ float sw[2 * NTAPS];
    if (threadIdx.x < 2 * NTAPS) sw[threadIdx.x] = weight[threadIdx.x];
    __syncthreads();

    int gtid = blockIdx.x * blockDim.x + threadIdx.x;
    int warp = gtid >> 5;
    int lane = threadIdx.x & 31;
    if (warp >= NPTS) return;

    int b = idx[warp * 3 + 0];
    int y = idx[warp * 3 + 1];
    int x = idx[warp * 3 + 2];
    const int* gb = g_grid + b * HWSZ;

    float acc = tap_contrib(lane, y, x, gb, sw);
    if (lane + 32 < NTAPS)
        acc += tap_contrib(lane + 32, y, x, gb, sw);

#pragma unroll
    for (int o = 16; o > 0; o >>= 1)
        acc += __shfl_xor_sync(0xFFFFFFFFu, acc, o);

    float conv = __shfl_sync(0xFFFFFFFFu, acc, 0);
    float sgm = 1.0f / (1.0f + __expf(-conv));

    float4 f = feat4[warp * 32 + lane];
    out4[warp * 32 + lane] = make_float4(sgm * f.x, sgm * f.y, sgm * f.z, sgm * f.w);
}

// ---------------------------------------------------------------------------
// Launch
// ---------------------------------------------------------------------------
extern "C" void kernel_launch(void* const* d_in, const int* in_sizes, int n_in,
                              void* d_out, int out_size) {
    // Positional fallback per reference signature: (features, weight, indices)
    const float* feat = (n_in > 0) ? (const float*)d_in[0] : nullptr;
    const float* w    = (n_in > 1) ? (const float*)d_in[1] : nullptr;
    const int*   idx  = (n_in > 2) ? (const int*)d_in[2]   : nullptr;
    // Prefer size-based identification when unambiguous.
    for (int i = 0; i < n_in; i++) {
        if (in_sizes[i] == NPTS * CCH)      feat = (const float*)d_in[i];
        else if (in_sizes[i] == 2 * NTAPS)  w    = (const float*)d_in[i];
        else if (in_sizes[i] == NPTS * 3)   idx  = (const int*)d_in[i];
    }

    const int threads = 256;

    // K0: grid reset. 214272 int4 stores -> 837 blocks * 256 threads exactly.
    fill_grid_kernel<<<(GRID_ELEMS / 4) / threads, threads>>>();

    // K1 / K2: one warp per point, 8 warps per 256-thread block.
    const int wpb = threads / 32;
    const int nblk = (NPTS + wpb - 1) / wpb;   // 50000

    reduce_scatter_kernel<<<nblk, threads>>>((const float4*)feat, idx);
    conv_scale_kernel<<<nblk, threads>>>((const float4*)feat, w, idx,
                                         (float4*)d_out);
}

// round 7
// speedup vs baseline: 1.1242x; 1.1242x over previous
#include <cuda_runtime.h>

// Problem constants (fixed by the reference)
#define BDIM  4
#define HDIM  496
#define WDIM  432
#define NPTS  400000
#define CCH   128
#define NTAPS 49                       // 7x7
#define PAD   3

// Padded spatial grid of (avg, max) pairs with a 3-cell zero halo on every side.
// Empty cells stay (0,0) and thus contribute exactly 0 to the conv (matches
// reference's `cat[nbr] * valid`). No bounds checks, no indirection.
#define PH (HDIM + 2 * PAD)            // 502
#define PW (WDIM + 2 * PAD)            // 438
#define GC_ELEMS (BDIM * PH * PW)      // 879504 float2 = 7.04 MB (L2-resident)
#define GC_FLOATS (GC_ELEMS * 2)       // 1759008, divisible by 4

__device__ float2 g_gridcat[GC_ELEMS];

// ---------------------------------------------------------------------------
// Kernel 0: zero the padded grid (float4 stores; graph-replayed each iter)
// ---------------------------------------------------------------------------
__global__ void __launch_bounds__(256) fill_grid_kernel() {
    int i = blockIdx.x * blockDim.x + threadIdx.x;
    if (i < GC_FLOATS / 4)
        reinterpret_cast<float4*>(g_gridcat)[i] = make_float4(0.f, 0.f, 0.f, 0.f);
}

// ---------------------------------------------------------------------------
// Kernel 1: per-point (mean, max) over 128 channels, scatter float2 into grid
// One warp per point. Lane l loads float4 = channels [4l, 4l+3].
// ---------------------------------------------------------------------------
__global__ void __launch_bounds__(256)
reduce_scatter_kernel(const float4* __restrict__ feat4,
                      const int*    __restrict__ idx) {
    int gtid = blockIdx.x * blockDim.x + threadIdx.x;
    int warp = gtid >> 5;
    int lane = threadIdx.x & 31;
    if (warp >= NPTS) return;

    float4 f = feat4[warp * 32 + lane];
    float s = (f.x + f.y) + (f.z + f.w);
    float m = fmaxf(fmaxf(f.x, f.y), fmaxf(f.z, f.w));
#pragma unroll
    for (int o = 16; o > 0; o >>= 1) {
        s += __shfl_xor_sync(0xFFFFFFFFu, s, o);
        m  = fmaxf(m, __shfl_xor_sync(0xFFFFFFFFu, m, o));
    }
    if (lane == 0) {
        int b = idx[warp * 3 + 0];
        int y = idx[warp * 3 + 1];
        int x = idx[warp * 3 + 2];
        g_gridcat[(b * PH + y + PAD) * PW + (x + PAD)] =
            make_float2(s * (1.0f / 128.0f), m);
    }
}

// ---------------------------------------------------------------------------
// Kernel 2: 7x7 unconditional gather of (avg,max), dot with weight, sigmoid,
// scale features. One warp per point; lane l takes taps l and l+32 (<49).
// base0 points at tap (dy=0,dx=0) of the padded grid: (b*PH + y)*PW + x.
// ---------------------------------------------------------------------------
__global__ void __launch_bounds__(256)
conv_scale_kernel(const float4* __restrict__ feat4,
                  const float*  __restrict__ weight,   // 98 floats, (49,2)
                  const int*    __restrict__ idx,
                  float4*       __restrict__ out4) {
    __shared__ float sw[2 * NTAPS];
    if (threadIdx.x < 2 * NTAPS) sw[threadIdx.x] = weight[threadIdx.x];
    __syncthreads();

    int gtid = blockIdx.x * blockDim.x + threadIdx.x;
    int warp = gtid >> 5;
    int lane = threadIdx.x & 31;
    if (warp >= NPTS) return;

    int b = idx[warp * 3 + 0];
    int y = idx[warp * 3 + 1];
    int x = idx[warp * 3 + 2];
    const float2* base0 = g_gridcat + (b * PH + y) * PW + x;

    // Tap 1: t = lane (always < 49 since lane < 32)
    float acc;
    {
        int t  = lane;
        int dy = t / 7;
        int dx = t - dy * 7;
        float2 c = __ldg(base0 + dy * PW + dx);
        acc = c.x * sw[2 * t] + c.y * sw[2 * t + 1];
    }
    // Tap 2: t = lane + 32 (lanes 0..16)
    if (lane < NTAPS - 32) {
        int t  = lane + 32;
        int dy = t / 7;
        int dx = t - dy * 7;
        float2 c = __ldg(base0 + dy * PW + dx);
        acc += c.x * sw[2 * t] + c.y * sw[2 * t + 1];
    }

#pragma unroll
    for (int o = 16; o > 0; o >>= 1)
        acc += __shfl_xor_sync(0xFFFFFFFFu, acc, o);

    float conv = __shfl_sync(0xFFFFFFFFu, acc, 0);
    float sgm = 1.0f / (1.0f + __expf(-conv));

    float4 f = feat4[warp * 32 + lane];
    out4[warp * 32 + lane] = make_float4(sgm * f.x, sgm * f.y, sgm * f.z, sgm * f.w);
}

// ---------------------------------------------------------------------------
// Launch
// ---------------------------------------------------------------------------
extern "C" void kernel_launch(void* const* d_in, const int* in_sizes, int n_in,
                              void* d_out, int out_size) {
    // Positional fallback per reference signature: (features, weight, indices)
    const float* feat = (n_in > 0) ? (const float*)d_in[0] : nullptr;
    const float* w    = (n_in > 1) ? (const float*)d_in[1] : nullptr;
    const int*   idx  = (n_in > 2) ? (const int*)d_in[2]   : nullptr;
    // Prefer size-based identification when unambiguous.
    for (int i = 0; i < n_in; i++) {
        if (in_sizes[i] == NPTS * CCH)      feat = (const float*)d_in[i];
        else if (in_sizes[i] == 2 * NTAPS)  w    = (const float*)d_in[i];
        else if (in_sizes[i] == NPTS * 3)   idx  = (const int*)d_in[i];
    }

    const int threads = 256;

    // K0: zero the padded grid (439752 float4 stores).
    fill_grid_kernel<<<(GC_FLOATS / 4 + threads - 1) / threads, threads>>>();

    // K1 / K2: one warp per point, 8 warps per 256-thread block.
    const int wpb = threads / 32;
    const int nblk = (NPTS + wpb - 1) / wpb;   // 50000

    reduce_scatter_kernel<<<nblk, threads>>>((const float4*)feat, idx);
    conv_scale_kernel<<<nblk, threads>>>((const float4*)feat, w, idx,
                                         (float4*)d_out);
}